// round 10
// baseline (speedup 1.0000x reference)
#include <cuda_runtime.h>
#include <cstdint>

#define NTHR   512
#define HEADS  64
#define TOPKN  512
#define KCH    128
#define SCALE_F 0.041666666666666664f
#define NEGINF __int_as_float(0xff800000)

#define N4 4718592   // (32768*576)/4 == (512*64*576)/4

__device__ __align__(16) uint2 g_kvh[N4];
__device__ __align__(16) uint2 g_kvl[N4];
__device__ __align__(16) uint2 g_qh[N4];
__device__ __align__(16) uint2 g_ql[N4];

// ---- smem byte offsets ----
#define OFF_IDX   0
#define OFF_M     2048
#define OFF_L     2304
#define OFF_C     2560
#define OFF_WMAX  2816
#define OFF_WSUM  3840
#define MB_KQ     4864                 // 3 mbarriers
#define MB_V      4888                 // 2 mbarriers
#define OFF_PH    5120                 // P: 64 rows * 272B; lo at +17408 (ends 39936)
#define OFF_PL    22528
#define KH_(s)    (39936 + (s)*36864)  // K slice: 128x144B hi; lo +18432 (3 stages, ends 150528)
#define QH_(s)    (150528 + (s)*18432) // Q slice: 64x144B hi; lo +9216 (3 stages, ends 205824)
#define VH_(i)    (39936 + (i)*36864)  // V tile: 16x1040B hi (16640B); lo +16640; sits on K stage i
#define SMEM_TOTAL 205824

__device__ __forceinline__ uint32_t smem_u32(const void* p) {
    uint32_t a;
    asm("{ .reg .u64 t; cvta.to.shared.u64 t, %1; cvt.u32.u64 %0, t; }" : "=r"(a) : "l"(p));
    return a;
}
__device__ __forceinline__ void split2(float x, float y, uint32_t& h2, uint32_t& l2) {
    uint32_t ux = __float_as_uint(x), uy = __float_as_uint(y);
    h2 = __byte_perm(ux, uy, 0x7632);
    float xl = x - __uint_as_float(ux & 0xffff0000u);
    float yl = y - __uint_as_float(uy & 0xffff0000u);
    asm("cvt.rn.bf16x2.f32 %0, %1, %2;" : "=r"(l2) : "f"(yl), "f"(xl));
}
__device__ __forceinline__ void ldsm4(uint32_t* r, uint32_t a) {
    asm volatile("ldmatrix.sync.aligned.m8n8.x4.shared.b16 {%0,%1,%2,%3}, [%4];"
                 : "=r"(r[0]), "=r"(r[1]), "=r"(r[2]), "=r"(r[3]) : "r"(a));
}
__device__ __forceinline__ void ldsm4t(uint32_t* r, uint32_t a) {
    asm volatile("ldmatrix.sync.aligned.m8n8.x4.trans.shared.b16 {%0,%1,%2,%3}, [%4];"
                 : "=r"(r[0]), "=r"(r[1]), "=r"(r[2]), "=r"(r[3]) : "r"(a));
}
__device__ __forceinline__ void mma16(float* d, const uint32_t* a, uint32_t b0, uint32_t b1) {
    asm volatile(
        "mma.sync.aligned.m16n8k16.row.col.f32.bf16.bf16.f32 "
        "{%0,%1,%2,%3}, {%4,%5,%6,%7}, {%8,%9}, {%0,%1,%2,%3};"
        : "+f"(d[0]), "+f"(d[1]), "+f"(d[2]), "+f"(d[3])
        : "r"(a[0]), "r"(a[1]), "r"(a[2]), "r"(a[3]), "r"(b0), "r"(b1));
}
__device__ __forceinline__ void bulk_cp(uint32_t dst, const void* src, uint32_t bytes, uint32_t mbar) {
    asm volatile(
        "cp.async.bulk.shared::cluster.global.mbarrier::complete_tx::bytes [%0], [%1], %2, [%3];"
        :: "r"(dst), "l"(src), "r"(bytes), "r"(mbar) : "memory");
}
__device__ __forceinline__ void expect_tx(uint32_t mbar, uint32_t bytes) {
    asm volatile("mbarrier.arrive.expect_tx.shared.b64 _, [%0], %1;"
                 :: "r"(mbar), "r"(bytes) : "memory");
}
__device__ __forceinline__ void mbar_wait(uint32_t mbar, uint32_t parity) {
    asm volatile(
        "{\n\t.reg .pred P;\n\t"
        "W%=:\n\t"
        "mbarrier.try_wait.parity.acquire.cta.shared::cta.b64 P, [%0], %1, 0x989680;\n\t"
        "@P bra.uni D%=;\n\t"
        "bra.uni W%=;\n\t"
        "D%=:\n\t}"
        :: "r"(mbar), "r"(parity) : "memory");
}

// ================= preprocessing: fp32 -> bf16 hi/lo =================
__global__ __launch_bounds__(256)
void conv_kernel(const float* __restrict__ kv, const float* __restrict__ qq)
{
    uint32_t i = blockIdx.x * 256u + threadIdx.x;
    const float* src;
    uint2 *dh, *dl;
    uint32_t o;
    if (i < N4) {
        o = i; src = kv + (size_t)o * 4; dh = g_kvh; dl = g_kvl;
    } else {
        o = i - N4; src = qq + (size_t)o * 4; dh = g_qh; dl = g_ql;
    }
    float4 v = *reinterpret_cast<const float4*>(src);
    uint32_t h0, l0, h1, l1;
    split2(v.x, v.y, h0, l0);
    split2(v.z, v.w, h1, l1);
    dh[o] = make_uint2(h0, h1);
    dl[o] = make_uint2(l0, l1);
}

// ================= bulk gather issue helpers =================
// K slice [128 keys x 64 d] + Q slice [64 heads x 64 d], one mbar per stage.
__device__ __forceinline__ void issue_kq(uint32_t smb, const int* idx_s,
                                         int ci, int ds, int t, int tid)
{
    const int st = ds % 3;
    const uint32_t mb = smb + MB_KQ + st * 8;
    if (tid == 0) expect_tx(mb, 49152);   // K 32768 + Q 16384
    if (tid < 128) {
        int gi = idx_s[ci * KCH + tid];
        if (gi < 0) gi = 0;               // masked later; any finite data ok
        size_t rb = (size_t)gi * 1152 + (size_t)ds * 128;
        uint32_t d = smb + KH_(st) + tid * 144;
        bulk_cp(d,         (const char*)g_kvh + rb, 128, mb);
        bulk_cp(d + 18432, (const char*)g_kvl + rb, 128, mb);
    } else if (tid < 192) {
        int row = tid - 128;
        size_t rb = ((size_t)t * 64 + row) * 1152 + (size_t)ds * 128;
        uint32_t d = smb + QH_(st) + row * 144;
        bulk_cp(d,        (const char*)g_qh + rb, 128, mb);
        bulk_cp(d + 9216, (const char*)g_ql + rb, 128, mb);
    }
}
// V tile [16 keys x 512 dv], buffer kst&1, one mbar per buffer.
__device__ __forceinline__ void issue_v(uint32_t smb, const int* idx_s,
                                        int ci, int kst, int tid)
{
    const int vb = kst & 1;
    const uint32_t mb = smb + MB_V + vb * 8;
    if (tid == 0) expect_tx(mb, 32768);
    if (tid < 16) {
        int gi = idx_s[ci * KCH + kst * 16 + tid];
        if (gi < 0) gi = 0;
        size_t rb = (size_t)gi * 1152;
        uint32_t d = smb + VH_(vb) + tid * 1040;
        bulk_cp(d,         (const char*)g_kvh + rb, 1024, mb);
        bulk_cp(d + 16640, (const char*)g_kvl + rb, 1024, mb);
    }
}

// ================= main attention kernel =================
__global__ __launch_bounds__(NTHR, 1)
void mla_mma_kernel(const int* __restrict__ topk,
                    const float* __restrict__ sink,
                    float* __restrict__ out)
{
    extern __shared__ char sm[];
    const uint32_t smb = smem_u32(sm);
    const int tid = threadIdx.x;
    const int w = tid >> 5, l = tid & 31;
    const int hg = w >> 2;
    const int kg = w & 3;
    const int t = blockIdx.x;

    int*   idx_s  = reinterpret_cast<int*>(sm + OFF_IDX);
    float* m_s    = reinterpret_cast<float*>(sm + OFF_M);
    float* l_s    = reinterpret_cast<float*>(sm + OFF_L);
    float* c_s    = reinterpret_cast<float*>(sm + OFF_C);
    float* wmax_s = reinterpret_cast<float*>(sm + OFF_WMAX);
    float* wsum_s = reinterpret_cast<float*>(sm + OFF_WSUM);

    idx_s[tid] = __ldg(topk + (size_t)t * TOPKN + tid);
    if (tid < HEADS) { m_s[tid] = __ldg(sink + tid); l_s[tid] = 1.f; }
    if (tid == 0) {
        #pragma unroll
        for (int i = 0; i < 5; ++i)
            asm volatile("mbarrier.init.shared.b64 [%0], 1;"
                         :: "r"(smb + MB_KQ + i * 8) : "memory");
    }
    __syncthreads();

    // per-stage phase counters
    int pk0 = 0, pk1 = 0, pk2 = 0, pv0 = 0, pv1 = 0;

    float o[16][4];
    #pragma unroll
    for (int i = 0; i < 16; ++i)
        #pragma unroll
        for (int j = 0; j < 4; ++j) o[i][j] = 0.f;

    // prologue: first two K/Q slices of chunk 0
    issue_kq(smb, idx_s, 0, 0, t, tid);
    issue_kq(smb, idx_s, 0, 1, t, tid);

    for (int ci = 0; ci < 4; ++ci) {
        float sacc[4][4];
        #pragma unroll
        for (int i = 0; i < 4; ++i)
            #pragma unroll
            for (int j = 0; j < 4; ++j) sacc[i][j] = 0.f;

        // ===== QK over 9 d-slices: bulk-copied, 3 stages, one sync/slice =====
        for (int ds = 0; ds < 9; ++ds) {
            const int st = ds % 3;
            int par = (st == 0) ? (pk0++ & 1) : (st == 1) ? (pk1++ & 1) : (pk2++ & 1);
            mbar_wait(smb + MB_KQ + st * 8, (uint32_t)par);
            __syncthreads();   // everyone done with stage (ds-1)%3 and past prev reads
            if (ds < 7) {
                issue_kq(smb, idx_s, ci, ds + 2, t, tid);
            } else if (ds == 8) {
                // K stages 0/1 free -> prefetch first two V tiles onto them
                issue_v(smb, idx_s, ci, 0, tid);
                issue_v(smb, idx_s, ci, 1, tid);
            }
            #pragma unroll
            for (int ks = 0; ks < 4; ++ks) {
                uint32_t qh[4], ql[4], kh[8], kl[8];
                uint32_t qa = smb + QH_(st) + (hg * 16 + (l & 15)) * 144 + (ks * 16 + (l >> 4) * 8) * 2;
                ldsm4(qh, qa);
                ldsm4(ql, qa + 9216);
                uint32_t ka = smb + KH_(st) + (kg * 32 + (l & 15)) * 144 + (ks * 16 + (l >> 4) * 8) * 2;
                ldsm4(kh, ka);
                ldsm4(kh + 4, ka + 16 * 144);
                ldsm4(kl, ka + 18432);
                ldsm4(kl + 4, ka + 18432 + 16 * 144);
                mma16(sacc[0], qh, kh[0], kh[2]); mma16(sacc[0], qh, kl[0], kl[2]); mma16(sacc[0], ql, kh[0], kh[2]);
                mma16(sacc[1], qh, kh[1], kh[3]); mma16(sacc[1], qh, kl[1], kl[3]); mma16(sacc[1], ql, kh[1], kh[3]);
                mma16(sacc[2], qh, kh[4], kh[6]); mma16(sacc[2], qh, kl[4], kl[6]); mma16(sacc[2], ql, kh[4], kh[6]);
                mma16(sacc[3], qh, kh[5], kh[7]); mma16(sacc[3], qh, kl[5], kl[7]); mma16(sacc[3], ql, kh[5], kh[7]);
            }
        }

        // ============ online softmax (register fragments) ============
        float rm0 = NEGINF, rm1 = NEGINF;
        #pragma unroll
        for (int nt = 0; nt < 4; ++nt) {
            int kb = ci * KCH + kg * 32 + nt * 8 + (l & 3) * 2;
            bool v0 = idx_s[kb] >= 0, v1 = idx_s[kb + 1] >= 0;
            float s0 = v0 ? sacc[nt][0] * SCALE_F : NEGINF;
            float s1 = v1 ? sacc[nt][1] * SCALE_F : NEGINF;
            float s2 = v0 ? sacc[nt][2] * SCALE_F : NEGINF;
            float s3 = v1 ? sacc[nt][3] * SCALE_F : NEGINF;
            sacc[nt][0] = s0; sacc[nt][1] = s1; sacc[nt][2] = s2; sacc[nt][3] = s3;
            rm0 = fmaxf(rm0, fmaxf(s0, s1));
            rm1 = fmaxf(rm1, fmaxf(s2, s3));
        }
        rm0 = fmaxf(rm0, __shfl_xor_sync(0xffffffffu, rm0, 1));
        rm0 = fmaxf(rm0, __shfl_xor_sync(0xffffffffu, rm0, 2));
        rm1 = fmaxf(rm1, __shfl_xor_sync(0xffffffffu, rm1, 1));
        rm1 = fmaxf(rm1, __shfl_xor_sync(0xffffffffu, rm1, 2));
        if ((l & 3) == 0) {
            wmax_s[kg * 64 + hg * 16 + (l >> 2)]     = rm0;
            wmax_s[kg * 64 + hg * 16 + 8 + (l >> 2)] = rm1;
        }
        __syncthreads();
        if (tid < HEADS) {
            float mo = m_s[tid];
            float mn = mo;
            #pragma unroll
            for (int g = 0; g < 4; ++g) mn = fmaxf(mn, wmax_s[g * 64 + tid]);
            float cr = __expf(mo - mn);
            m_s[tid] = mn; c_s[tid] = cr; l_s[tid] *= cr;
        }
        __syncthreads();
        float mr0 = m_s[hg * 16 + (l >> 2)];
        float mr1 = m_s[hg * 16 + 8 + (l >> 2)];
        float sum0 = 0.f, sum1 = 0.f;
        #pragma unroll
        for (int nt = 0; nt < 4; ++nt) {
            float e0 = __expf(sacc[nt][0] - mr0);
            float e1 = __expf(sacc[nt][1] - mr0);
            float e2 = __expf(sacc[nt][2] - mr1);
            float e3 = __expf(sacc[nt][3] - mr1);
            sum0 += e0 + e1; sum1 += e2 + e3;
            uint32_t ha, la, hb, lb;
            split2(e0, e1, ha, la);
            split2(e2, e3, hb, lb);
            uint32_t col = (uint32_t)(kg * 32 + nt * 8 + (l & 3) * 2) * 2;
            uint32_t r0o = (uint32_t)(hg * 16 + (l >> 2)) * 272 + col;
            uint32_t r1o = r0o + 8 * 272;
            *reinterpret_cast<uint32_t*>(sm + OFF_PH + r0o) = ha;
            *reinterpret_cast<uint32_t*>(sm + OFF_PL + r0o) = la;
            *reinterpret_cast<uint32_t*>(sm + OFF_PH + r1o) = hb;
            *reinterpret_cast<uint32_t*>(sm + OFF_PL + r1o) = lb;
        }
        sum0 += __shfl_xor_sync(0xffffffffu, sum0, 1);
        sum0 += __shfl_xor_sync(0xffffffffu, sum0, 2);
        sum1 += __shfl_xor_sync(0xffffffffu, sum1, 1);
        sum1 += __shfl_xor_sync(0xffffffffu, sum1, 2);
        if ((l & 3) == 0) {
            wsum_s[kg * 64 + hg * 16 + (l >> 2)]     = sum0;
            wsum_s[kg * 64 + hg * 16 + 8 + (l >> 2)] = sum1;
        }
        __syncthreads();
        if (tid < HEADS)
            l_s[tid] += wsum_s[tid] + wsum_s[64 + tid] + wsum_s[128 + tid] + wsum_s[192 + tid];
        float c0 = c_s[hg * 16 + (l >> 2)];
        float c1 = c_s[hg * 16 + 8 + (l >> 2)];
        #pragma unroll
        for (int nt = 0; nt < 16; ++nt) {
            o[nt][0] *= c0; o[nt][1] *= c0; o[nt][2] *= c1; o[nt][3] *= c1;
        }
        __syncthreads();   // P writes visible to all before PV ldsm

        // ===== PV over 8 key-steps of 16 keys, bulk-copied, 2 buffers =====
        for (int kst = 0; kst < 8; ++kst) {
            const int vb = kst & 1;
            int par = vb ? (pv1++ & 1) : (pv0++ & 1);
            mbar_wait(smb + MB_V + vb * 8, (uint32_t)par);
            uint32_t ph[4], pl[4];
            uint32_t pa = smb + OFF_PH + (hg * 16 + (l & 15)) * 272 +
                          (kst * 16 + (l >> 4) * 8) * 2;
            ldsm4(ph, pa);
            ldsm4(pl, pa + 17408);
            #pragma unroll
            for (int dvt = 0; dvt < 8; ++dvt) {
                uint32_t vh[4], vl[4];
                uint32_t va = smb + VH_(vb) + (l & 15) * 1040 +
                              (kg * 128 + dvt * 16 + (l >> 4) * 8) * 2;
                ldsm4t(vh, va);
                ldsm4t(vl, va + 16640);
                float* o0 = o[dvt * 2];
                float* o1 = o[dvt * 2 + 1];
                mma16(o0, ph, vh[0], vh[1]); mma16(o0, ph, vl[0], vl[1]); mma16(o0, pl, vh[0], vh[1]);
                mma16(o1, ph, vh[2], vh[3]); mma16(o1, ph, vl[2], vl[3]); mma16(o1, pl, vh[2], vh[3]);
            }
            __syncthreads();   // all warps done reading buffer vb
            if (kst < 6) {
                issue_v(smb, idx_s, ci, kst + 2, tid);
            } else if (kst == 6 && ci < 3) {
                issue_kq(smb, idx_s, ci + 1, 0, t, tid);   // stage0 region == V buf0 (free)
            } else if (kst == 7 && ci < 3) {
                issue_kq(smb, idx_s, ci + 1, 1, t, tid);   // stage1 region == V buf1 (free)
            }
        }
    }

    // ============ epilogue ============
    float n0 = 1.f / l_s[hg * 16 + (l >> 2)];
    float n1 = 1.f / l_s[hg * 16 + 8 + (l >> 2)];
    float* ob0 = out + ((size_t)t * HEADS + hg * 16 + (l >> 2)) * 512;
    float* ob1 = ob0 + 8 * 512;
    #pragma unroll
    for (int nt = 0; nt < 16; ++nt) {
        int dv = kg * 128 + nt * 8 + (l & 3) * 2;
        *reinterpret_cast<float2*>(ob0 + dv) = make_float2(o[nt][0] * n0, o[nt][1] * n0);
        *reinterpret_cast<float2*>(ob1 + dv) = make_float2(o[nt][2] * n1, o[nt][3] * n1);
    }
}

extern "C" void kernel_launch(void* const* d_in, const int* in_sizes, int n_in,
                              void* d_out, int out_size)
{
    const float* q    = (const float*)d_in[0];
    const float* kv   = (const float*)d_in[1];
    const int*   topk = (const int*)d_in[2];
    const float* sink = (const float*)d_in[3];
    float* out = (float*)d_out;

    conv_kernel<<<(2 * N4) / 256, 256>>>(kv, q);

    cudaFuncSetAttribute(mla_mma_kernel, cudaFuncAttributeMaxDynamicSharedMemorySize, SMEM_TOTAL);
    mla_mma_kernel<<<512, NTHR, SMEM_TOTAL>>>(topk, sink, out);
}

// round 11
// speedup vs baseline: 1.2157x; 1.2157x over previous
#include <cuda_runtime.h>
#include <cuda_fp16.h>
#include <cstdint>

#define NTHR   512
#define HEADS  64
#define TOPKN  512
#define SCALE_F 0.041666666666666664f
#define NEGINF __int_as_float(0xff800000)

#define N2 4718592   // uint2 count: 32768*576*2B/8 == 512*64*576*2B/8

__device__ __align__(16) uint2 g_kh[N2];   // kv fp16 hi
__device__ __align__(16) uint2 g_kl[N2];   // kv fp16 lo (residual)
__device__ __align__(16) uint2 g_q[N2];    // q fp16 (single)

// ---- smem byte offsets ----
#define OFF_IDX   0                      // 512*4
#define OFF_M     2048                   // 64*4
#define OFF_L     2304                   // 64*4 (holds 1/l)
#define OFF_WMAX  2560                   // 4*64*4
#define OFF_WSUM  3584                   // 4*64*4, ends 4608
#define PH_(b)    (4608 + (b)*17408)     // P fp16: 64 rows * 272B, 2 bufs, ends 39424
#define KH_(s)    (39424 + (s)*36864)    // K slice: 128 rows*144B hi; lo +18432; 3 stages, ends 150016
#define QH_(s)    (150016 + (s)*9216)    // Q slice: 64 rows*144B (fp16 hi only); 2 stages, ends 168448
#define VH_(i)    (39424 + (i)*36864)    // V tile: 16 rows*1040B hi; lo +16640; on K stage i
#define SMEM_TOTAL 168448

__device__ __forceinline__ uint32_t smem_u32(const void* p) {
    uint32_t a;
    asm("{ .reg .u64 t; cvta.to.shared.u64 t, %1; cvt.u32.u64 %0, t; }" : "=r"(a) : "l"(p));
    return a;
}
__device__ __forceinline__ void ldsm4(uint32_t* r, uint32_t a) {
    asm volatile("ldmatrix.sync.aligned.m8n8.x4.shared.b16 {%0,%1,%2,%3}, [%4];"
                 : "=r"(r[0]), "=r"(r[1]), "=r"(r[2]), "=r"(r[3]) : "r"(a));
}
__device__ __forceinline__ void ldsm4t(uint32_t* r, uint32_t a) {
    asm volatile("ldmatrix.sync.aligned.m8n8.x4.trans.shared.b16 {%0,%1,%2,%3}, [%4];"
                 : "=r"(r[0]), "=r"(r[1]), "=r"(r[2]), "=r"(r[3]) : "r"(a));
}
__device__ __forceinline__ void mma16f(float* d, const uint32_t* a, uint32_t b0, uint32_t b1) {
    asm volatile(
        "mma.sync.aligned.m16n8k16.row.col.f32.f16.f16.f32 "
        "{%0,%1,%2,%3}, {%4,%5,%6,%7}, {%8,%9}, {%0,%1,%2,%3};"
        : "+f"(d[0]), "+f"(d[1]), "+f"(d[2]), "+f"(d[3])
        : "r"(a[0]), "r"(a[1]), "r"(a[2]), "r"(a[3]), "r"(b0), "r"(b1));
}
__device__ __forceinline__ void cpa(uint32_t dst, const void* src, uint32_t sz) {
    asm volatile("cp.async.cg.shared.global [%0], [%1], 16, %2;"
                 :: "r"(dst), "l"(src), "r"(sz) : "memory");
}
#define CP_COMMIT() asm volatile("cp.async.commit_group;" ::: "memory")
#define CP_WAIT(n)  asm volatile("cp.async.wait_group %0;" :: "n"(n) : "memory")

__device__ __forceinline__ uint32_t packh2(float x, float y) {
    uint32_t r;
    asm("cvt.rn.f16x2.f32 %0, %1, %2;" : "=r"(r) : "f"(y), "f"(x));  // x -> low half
    return r;
}

// ================= preprocessing: fp32 -> fp16 hi/lo (kv), fp16 (q) =================
__global__ __launch_bounds__(256)
void conv_kernel(const float* __restrict__ kv, const float* __restrict__ qq)
{
    uint32_t i = blockIdx.x * 256u + threadIdx.x;
    if (i < N2) {
        float4 v = *reinterpret_cast<const float4*>(kv + (size_t)i * 4);
        __half hx = __float2half_rn(v.x), hy = __float2half_rn(v.y);
        __half hz = __float2half_rn(v.z), hw = __float2half_rn(v.w);
        g_kh[i] = make_uint2(packh2(__half2float(hx), __half2float(hy)),
                             packh2(__half2float(hz), __half2float(hw)));
        g_kl[i] = make_uint2(packh2(v.x - __half2float(hx), v.y - __half2float(hy)),
                             packh2(v.z - __half2float(hz), v.w - __half2float(hw)));
    } else {
        uint32_t o = i - N2;
        float4 v = *reinterpret_cast<const float4*>(qq + (size_t)o * 4);
        g_q[o] = make_uint2(packh2(v.x, v.y), packh2(v.z, v.w));
    }
}

// ================= gather issue helpers =================
// K slice for iteration it (ds = it>>2, chunk ci = it&3): [128 keys x 64 d], fp16 hi+lo.
// Q slice for ds issued together when ci==0.
__device__ __forceinline__ void issue_g(uint32_t smb, const int* idx_s, int it, int t, int tid)
{
    const int ds = it >> 2, ci = it & 3, st = it % 3;
    {
        int row = tid >> 2, sub = tid & 3;
        int gi = idx_s[ci * 128 + row];
        uint32_t sz = gi >= 0 ? 16u : 0u;
        if (gi < 0) gi = 0;
        size_t rb = (size_t)gi * 1152 + (size_t)ds * 128 + sub * 32;
        uint32_t d = smb + KH_(st) + row * 144 + sub * 32;
        cpa(d,              (const char*)g_kh + rb,      sz);
        cpa(d + 16,         (const char*)g_kh + rb + 16, sz);
        cpa(d + 18432,      (const char*)g_kl + rb,      sz);
        cpa(d + 18432 + 16, (const char*)g_kl + rb + 16, sz);
    }
    if (ci == 0) {
        int row = tid >> 3, sub = tid & 7;
        size_t rb = ((size_t)t * 64 + row) * 1152 + (size_t)ds * 128 + sub * 16;
        cpa(smb + QH_(ds & 1) + row * 144 + sub * 16, (const char*)g_q + rb, 16);
    }
}
// V tile kst2 (global, 0..31): [16 keys x 512 dv] fp16 hi+lo, buffer kst2&1.
__device__ __forceinline__ void issue_v(uint32_t smb, const int* idx_s, int kst2, int tid)
{
    if (tid < 256) {
        int row = tid >> 4, sub = tid & 15;
        int gi = idx_s[kst2 * 16 + row];
        uint32_t sz = gi >= 0 ? 16u : 0u;
        if (gi < 0) gi = 0;
        size_t rb = (size_t)gi * 1152 + sub * 64;
        uint32_t d = smb + VH_(kst2 & 1) + row * 1040 + sub * 64;
        #pragma unroll
        for (int j = 0; j < 4; ++j) {
            cpa(d + j * 16,         (const char*)g_kh + rb + j * 16, sz);
            cpa(d + 16640 + j * 16, (const char*)g_kl + rb + j * 16, sz);
        }
    }
}

// ================= main attention kernel =================
__global__ __launch_bounds__(NTHR, 1)
void mla_mma_kernel(const int* __restrict__ topk,
                    const float* __restrict__ sink,
                    float* __restrict__ out)
{
    extern __shared__ char sm[];
    const uint32_t smb = smem_u32(sm);
    const int tid = threadIdx.x;
    const int w = tid >> 5, l = tid & 31;
    const int hg = w >> 2;          // 4 head groups of 16
    const int kg = w & 3;           // QK: 32-key group; PV: 128-dv group
    const int t = blockIdx.x;

    int*   idx_s  = reinterpret_cast<int*>(sm + OFF_IDX);
    float* m_s    = reinterpret_cast<float*>(sm + OFF_M);
    float* l_s    = reinterpret_cast<float*>(sm + OFF_L);
    float* wmax_s = reinterpret_cast<float*>(sm + OFF_WMAX);
    float* wsum_s = reinterpret_cast<float*>(sm + OFF_WSUM);

    idx_s[tid] = __ldg(topk + (size_t)t * TOPKN + tid);
    if (tid < HEADS) m_s[tid] = __ldg(sink + tid);
    __syncthreads();

    // ===== QK: ds-outer (9 d-slices), ci-inner (4 chunks); all scores in regs =====
    float sacc[16][4];
    #pragma unroll
    for (int i = 0; i < 16; ++i)
        #pragma unroll
        for (int j = 0; j < 4; ++j) sacc[i][j] = 0.f;

    issue_g(smb, idx_s, 0, t, tid); CP_COMMIT();
    issue_g(smb, idx_s, 1, t, tid); CP_COMMIT();
    for (int it = 0; it < 36; ++it) {
        if (it < 35) CP_WAIT(1); else CP_WAIT(0);
        __syncthreads();                 // data(it) ready + all warps past reads of it-1
        if (it <= 33) { issue_g(smb, idx_s, it + 2, t, tid); CP_COMMIT(); }
        const int ci = it & 3, st = it % 3, qs = (it >> 2) & 1;
        float* s0 = sacc[ci * 4 + 0];
        float* s1 = sacc[ci * 4 + 1];
        float* s2 = sacc[ci * 4 + 2];
        float* s3 = sacc[ci * 4 + 3];
        #pragma unroll
        for (int ks = 0; ks < 4; ++ks) {
            uint32_t qf[4], kh[8], kl[8];
            uint32_t qa = smb + QH_(qs) + (hg * 16 + (l & 15)) * 144 + (ks * 16 + (l >> 4) * 8) * 2;
            ldsm4(qf, qa);
            uint32_t ka = smb + KH_(st) + (kg * 32 + (l & 15)) * 144 + (ks * 16 + (l >> 4) * 8) * 2;
            ldsm4(kh, ka);
            ldsm4(kh + 4, ka + 16 * 144);
            ldsm4(kl, ka + 18432);
            ldsm4(kl + 4, ka + 18432 + 16 * 144);
            mma16f(s0, qf, kh[0], kh[2]); mma16f(s0, qf, kl[0], kl[2]);
            mma16f(s1, qf, kh[1], kh[3]); mma16f(s1, qf, kl[1], kl[3]);
            mma16f(s2, qf, kh[4], kh[6]); mma16f(s2, qf, kl[4], kl[6]);
            mma16f(s3, qf, kh[5], kh[7]); mma16f(s3, qf, kl[5], kl[7]);
        }
    }

    // prefetch first two V tiles (K stages 0/1 are free: all warps past it=34)
    issue_v(smb, idx_s, 0, tid); CP_COMMIT();
    issue_v(smb, idx_s, 1, tid); CP_COMMIT();

    // ===== single global softmax over all 512 keys (scores in regs) =====
    {
        float rm0 = NEGINF, rm1 = NEGINF;
        #pragma unroll
        for (int i = 0; i < 16; ++i) {
            int ci = i >> 2, nt = i & 3;
            int kb = ci * 128 + kg * 32 + nt * 8 + (l & 3) * 2;
            bool v0 = idx_s[kb] >= 0, v1 = idx_s[kb + 1] >= 0;
            float a0 = v0 ? sacc[i][0] * SCALE_F : NEGINF;
            float a1 = v1 ? sacc[i][1] * SCALE_F : NEGINF;
            float a2 = v0 ? sacc[i][2] * SCALE_F : NEGINF;
            float a3 = v1 ? sacc[i][3] * SCALE_F : NEGINF;
            sacc[i][0] = a0; sacc[i][1] = a1; sacc[i][2] = a2; sacc[i][3] = a3;
            rm0 = fmaxf(rm0, fmaxf(a0, a1));
            rm1 = fmaxf(rm1, fmaxf(a2, a3));
        }
        rm0 = fmaxf(rm0, __shfl_xor_sync(0xffffffffu, rm0, 1));
        rm0 = fmaxf(rm0, __shfl_xor_sync(0xffffffffu, rm0, 2));
        rm1 = fmaxf(rm1, __shfl_xor_sync(0xffffffffu, rm1, 1));
        rm1 = fmaxf(rm1, __shfl_xor_sync(0xffffffffu, rm1, 2));
        if ((l & 3) == 0) {
            wmax_s[kg * 64 + hg * 16 + (l >> 2)]     = rm0;
            wmax_s[kg * 64 + hg * 16 + 8 + (l >> 2)] = rm1;
        }
        __syncthreads();
        if (tid < HEADS) {
            float mn = m_s[tid];   // starts at sink
            #pragma unroll
            for (int g = 0; g < 4; ++g) mn = fmaxf(mn, wmax_s[g * 64 + tid]);
            m_s[tid] = mn;
        }
        __syncthreads();
        float mr0 = m_s[hg * 16 + (l >> 2)];
        float mr1 = m_s[hg * 16 + 8 + (l >> 2)];
        float sum0 = 0.f, sum1 = 0.f;
        #pragma unroll
        for (int i = 0; i < 16; ++i) {
            float e0 = __expf(sacc[i][0] - mr0);
            float e1 = __expf(sacc[i][1] - mr0);
            float e2 = __expf(sacc[i][2] - mr1);
            float e3 = __expf(sacc[i][3] - mr1);
            sacc[i][0] = e0; sacc[i][1] = e1; sacc[i][2] = e2; sacc[i][3] = e3;
            sum0 += e0 + e1; sum1 += e2 + e3;
        }
        sum0 += __shfl_xor_sync(0xffffffffu, sum0, 1);
        sum0 += __shfl_xor_sync(0xffffffffu, sum0, 2);
        sum1 += __shfl_xor_sync(0xffffffffu, sum1, 1);
        sum1 += __shfl_xor_sync(0xffffffffu, sum1, 2);
        if ((l & 3) == 0) {
            wsum_s[kg * 64 + hg * 16 + (l >> 2)]     = sum0;
            wsum_s[kg * 64 + hg * 16 + 8 + (l >> 2)] = sum1;
        }
        __syncthreads();
        if (tid < HEADS) {
            float den = wsum_s[tid] + wsum_s[64 + tid] + wsum_s[128 + tid] + wsum_s[192 + tid]
                      + __expf(__ldg(sink + tid) - m_s[tid]);
            l_s[tid] = 1.f / den;
        }
    }

    // write P for chunks 0,1 (fp16, bufs 0/1); visible via PV's first sync
    #pragma unroll
    for (int ci = 0; ci < 2; ++ci) {
        #pragma unroll
        for (int nt = 0; nt < 4; ++nt) {
            float* s = sacc[ci * 4 + nt];
            uint32_t col = (uint32_t)(kg * 32 + nt * 8 + (l & 3) * 2) * 2;
            uint32_t r0o = (uint32_t)(hg * 16 + (l >> 2)) * 272 + col;
            *reinterpret_cast<uint32_t*>(sm + PH_(ci) + r0o)           = packh2(s[0], s[1]);
            *reinterpret_cast<uint32_t*>(sm + PH_(ci) + r0o + 8 * 272) = packh2(s[2], s[3]);
        }
    }

    // ===== PV: 32 V tiles of 16 keys, fp16 2-pass, double-buffered =====
    float o[16][4];
    #pragma unroll
    for (int i = 0; i < 16; ++i)
        #pragma unroll
        for (int j = 0; j < 4; ++j) o[i][j] = 0.f;

    for (int kst2 = 0; kst2 < 32; ++kst2) {
        if (kst2 < 30) CP_WAIT(1); else CP_WAIT(0);
        __syncthreads();
        const int ci = kst2 >> 3, vb = kst2 & 1, kst = kst2 & 7;
        uint32_t ph[4];
        uint32_t pa = smb + PH_(ci & 1) + (hg * 16 + (l & 15)) * 272 +
                      (kst * 16 + (l >> 4) * 8) * 2;
        ldsm4(ph, pa);
        #pragma unroll
        for (int dvt = 0; dvt < 8; ++dvt) {
            uint32_t vh[4], vl[4];
            uint32_t va = smb + VH_(vb) + (l & 15) * 1040 +
                          (kg * 128 + dvt * 16 + (l >> 4) * 8) * 2;
            ldsm4t(vh, va);
            ldsm4t(vl, va + 16640);
            float* o0 = o[dvt * 2];
            float* o1 = o[dvt * 2 + 1];
            mma16f(o0, ph, vh[0], vh[1]); mma16f(o0, ph, vl[0], vl[1]);
            mma16f(o1, ph, vh[2], vh[3]); mma16f(o1, ph, vl[2], vl[3]);
        }
        __syncthreads();   // all warps done with buffer vb and P buf (at seams)
        if (kst2 < 30) { issue_v(smb, idx_s, kst2 + 2, tid); CP_COMMIT(); }
        if (kst2 == 7 || kst2 == 15) {   // P buf (kst2==7 -> chunk2 into buf0; 15 -> chunk3 into buf1)
            const int cw = (kst2 == 7) ? 2 : 3;
            #pragma unroll
            for (int nt = 0; nt < 4; ++nt) {
                float* s = sacc[cw * 4 + nt];
                uint32_t col = (uint32_t)(kg * 32 + nt * 8 + (l & 3) * 2) * 2;
                uint32_t r0o = (uint32_t)(hg * 16 + (l >> 2)) * 272 + col;
                *reinterpret_cast<uint32_t*>(sm + PH_(cw & 1) + r0o)           = packh2(s[0], s[1]);
                *reinterpret_cast<uint32_t*>(sm + PH_(cw & 1) + r0o + 8 * 272) = packh2(s[2], s[3]);
            }
        }
    }

    // ============ epilogue: normalize + store ============
    float n0 = l_s[hg * 16 + (l >> 2)];
    float n1 = l_s[hg * 16 + 8 + (l >> 2)];
    float* ob0 = out + ((size_t)t * HEADS + hg * 16 + (l >> 2)) * 512;
    float* ob1 = ob0 + 8 * 512;
    #pragma unroll
    for (int nt = 0; nt < 16; ++nt) {
        int dv = kg * 128 + nt * 8 + (l & 3) * 2;
        *reinterpret_cast<float2*>(ob0 + dv) = make_float2(o[nt][0] * n0, o[nt][1] * n0);
        *reinterpret_cast<float2*>(ob1 + dv) = make_float2(o[nt][2] * n1, o[nt][3] * n1);
    }
}

extern "C" void kernel_launch(void* const* d_in, const int* in_sizes, int n_in,
                              void* d_out, int out_size)
{
    const float* q    = (const float*)d_in[0];
    const float* kv   = (const float*)d_in[1];
    const int*   topk = (const int*)d_in[2];
    const float* sink = (const float*)d_in[3];
    float* out = (float*)d_out;

    conv_kernel<<<(2 * N2) / 256, 256>>>(kv, q);

    cudaFuncSetAttribute(mla_mma_kernel, cudaFuncAttributeMaxDynamicSharedMemorySize, SMEM_TOTAL);
    mla_mma_kernel<<<512, NTHR, SMEM_TOTAL>>>(topk, sink, out);
}

// round 13
// speedup vs baseline: 1.5742x; 1.2949x over previous
#include <cuda_runtime.h>
#include <cuda_fp16.h>
#include <cstdint>

#define NTHR   1024
#define HEADS  64
#define TOPKN  512
#define SCALE_F 0.041666666666666664f
#define NEGINF __int_as_float(0xff800000)

#define N2 4718592   // uint2 count: 32768*576*2B/8 == 512*64*576*2B/8

__device__ __align__(16) uint2 g_kh[N2];   // kv fp16 hi
__device__ __align__(16) uint2 g_kl[N2];   // kv fp16 lo (residual)
__device__ __align__(16) uint2 g_q[N2];    // q fp16

// ---- smem byte offsets ----
#define OFF_IDX   0                       // 512*4
#define OFF_M     2048
#define OFF_L     2304
#define OFF_C     2560
#define OFF_WMAX  2816                    // 8*64*4 -> 4864
#define OFF_WSUM  4864                    // 8*64*4 -> 6912
#define OFF_P     6912                    // P fp16: 64 rows * 272B -> 24320
#define KH_(s)    (24320 + (s)*36864)     // K slice 128x144B hi; lo +18432; 3 stages -> 134912
#define QH_(s)    (134912 + (s)*9216)     // Q slice 64x144B fp16 hi; 3 stages -> 162560
#define VH_(i)    (24320 + (i)*36864)     // V tile 16x1040B hi; lo +16640; on K stage i
#define SMEM_TOTAL 162560

__device__ __forceinline__ uint32_t smem_u32(const void* p) {
    uint32_t a;
    asm("{ .reg .u64 t; cvta.to.shared.u64 t, %1; cvt.u32.u64 %0, t; }" : "=r"(a) : "l"(p));
    return a;
}
__device__ __forceinline__ void ldsm4(uint32_t* r, uint32_t a) {
    asm volatile("ldmatrix.sync.aligned.m8n8.x4.shared.b16 {%0,%1,%2,%3}, [%4];"
                 : "=r"(r[0]), "=r"(r[1]), "=r"(r[2]), "=r"(r[3]) : "r"(a));
}
__device__ __forceinline__ void ldsm4t(uint32_t* r, uint32_t a) {
    asm volatile("ldmatrix.sync.aligned.m8n8.x4.trans.shared.b16 {%0,%1,%2,%3}, [%4];"
                 : "=r"(r[0]), "=r"(r[1]), "=r"(r[2]), "=r"(r[3]) : "r"(a));
}
__device__ __forceinline__ void mma16f(float* d, const uint32_t* a, uint32_t b0, uint32_t b1) {
    asm volatile(
        "mma.sync.aligned.m16n8k16.row.col.f32.f16.f16.f32 "
        "{%0,%1,%2,%3}, {%4,%5,%6,%7}, {%8,%9}, {%0,%1,%2,%3};"
        : "+f"(d[0]), "+f"(d[1]), "+f"(d[2]), "+f"(d[3])
        : "r"(a[0]), "r"(a[1]), "r"(a[2]), "r"(a[3]), "r"(b0), "r"(b1));
}
__device__ __forceinline__ void cpa(uint32_t dst, const void* src, uint32_t sz) {
    asm volatile("cp.async.cg.shared.global [%0], [%1], 16, %2;"
                 :: "r"(dst), "l"(src), "r"(sz) : "memory");
}
#define CP_COMMIT() asm volatile("cp.async.commit_group;" ::: "memory")
#define CP_WAIT(n)  asm volatile("cp.async.wait_group %0;" :: "n"(n) : "memory")

__device__ __forceinline__ uint32_t packh2(float x, float y) {
    uint32_t r;
    asm("cvt.rn.f16x2.f32 %0, %1, %2;" : "=r"(r) : "f"(y), "f"(x));  // x -> low half
    return r;
}

// ================= preprocessing: fp32 -> fp16 hi/lo (kv), fp16 (q) =================
__global__ __launch_bounds__(256)
void conv_kernel(const float* __restrict__ kv, const float* __restrict__ qq)
{
    uint32_t i = blockIdx.x * 256u + threadIdx.x;
    if (i < N2) {
        float4 v = *reinterpret_cast<const float4*>(kv + (size_t)i * 4);
        __half hx = __float2half_rn(v.x), hy = __float2half_rn(v.y);
        __half hz = __float2half_rn(v.z), hw = __float2half_rn(v.w);
        g_kh[i] = make_uint2(packh2(__half2float(hx), __half2float(hy)),
                             packh2(__half2float(hz), __half2float(hw)));
        g_kl[i] = make_uint2(packh2(v.x - __half2float(hx), v.y - __half2float(hy)),
                             packh2(v.z - __half2float(hz), v.w - __half2float(hw)));
    } else {
        uint32_t o = i - N2;
        float4 v = *reinterpret_cast<const float4*>(qq + (size_t)o * 4);
        g_q[o] = make_uint2(packh2(v.x, v.y), packh2(v.z, v.w));
    }
}

// ================= gather issue helpers (1024 threads) =================
__device__ __forceinline__ void issue_kq(uint32_t smb, const int* idx_s,
                                         int ci, int ds, int t, int tid)
{
    const int st = ds % 3;
    {   // K slice [128 keys x 64 d]: 8 threads/row, 16B hi + 16B lo each
        int row = tid >> 3, sub = tid & 7;
        int gi = idx_s[ci * 128 + row];
        uint32_t sz = gi >= 0 ? 16u : 0u;
        if (gi < 0) gi = 0;
        size_t rb = (size_t)gi * 1152 + (size_t)ds * 128 + sub * 16;
        uint32_t d = smb + KH_(st) + row * 144 + sub * 16;
        cpa(d,         (const char*)g_kh + rb, sz);
        cpa(d + 18432, (const char*)g_kl + rb, sz);
    }
    if (tid < 512) {   // Q slice [64 heads x 64 d] fp16 hi, 3-stage
        int row = tid >> 3, sub = tid & 7;
        size_t rb = ((size_t)t * 64 + row) * 1152 + (size_t)ds * 128 + sub * 16;
        cpa(smb + QH_(st) + row * 144 + sub * 16, (const char*)g_q + rb, 16);
    }
}
__device__ __forceinline__ void issue_v(uint32_t smb, const int* idx_s,
                                        int ci, int kst, int tid)
{
    // V tile [16 keys x 512 dv]: 64 threads/row, 16B hi + 16B lo each
    int row = tid >> 6, sub = tid & 63;
    int gi = idx_s[ci * 128 + kst * 16 + row];
    uint32_t sz = gi >= 0 ? 16u : 0u;
    if (gi < 0) gi = 0;
    size_t rb = (size_t)gi * 1152 + sub * 16;
    uint32_t d = smb + VH_(kst & 1) + row * 1040 + sub * 16;
    cpa(d,         (const char*)g_kh + rb, sz);
    cpa(d + 16640, (const char*)g_kl + rb, sz);
}

// ================= main attention kernel =================
__global__ __launch_bounds__(NTHR, 1)
void mla_mma_kernel(const int* __restrict__ topk,
                    const float* __restrict__ sink,
                    float* __restrict__ out)
{
    extern __shared__ char sm[];
    const uint32_t smb = smem_u32(sm);
    const int tid = threadIdx.x;
    const int w = tid >> 5, l = tid & 31;
    const int hg = w >> 3;          // 4 head groups of 16
    const int kg = w & 7;           // QK: 16-key group; PV: 64-dv group
    const int t = blockIdx.x;

    int*   idx_s  = reinterpret_cast<int*>(sm + OFF_IDX);
    float* m_s    = reinterpret_cast<float*>(sm + OFF_M);
    float* l_s    = reinterpret_cast<float*>(sm + OFF_L);
    float* c_s    = reinterpret_cast<float*>(sm + OFF_C);
    float* wmax_s = reinterpret_cast<float*>(sm + OFF_WMAX);
    float* wsum_s = reinterpret_cast<float*>(sm + OFF_WSUM);

    if (tid < 512) idx_s[tid] = __ldg(topk + (size_t)t * TOPKN + tid);
    if (tid < HEADS) { m_s[tid] = __ldg(sink + tid); l_s[tid] = 1.f; }
    __syncthreads();

    float o[8][4];
    #pragma unroll
    for (int i = 0; i < 8; ++i)
        #pragma unroll
        for (int j = 0; j < 4; ++j) o[i][j] = 0.f;

    issue_kq(smb, idx_s, 0, 0, t, tid); CP_COMMIT();
    issue_kq(smb, idx_s, 0, 1, t, tid); CP_COMMIT();

    for (int ci = 0; ci < 4; ++ci) {
        float sacc[2][4];
        #pragma unroll
        for (int i = 0; i < 2; ++i)
            #pragma unroll
            for (int j = 0; j < 4; ++j) sacc[i][j] = 0.f;

        // ===== QK: 9 d-slices of 64, 3-stage pipeline (K and Q both 3-stage) =====
        for (int ds = 0; ds < 9; ++ds) {
            if (ds < 8) CP_WAIT(1); else CP_WAIT(0);
            __syncthreads();   // data(ds) visible + all warps done with stage (ds-1)%3
            if (ds < 7) {
                issue_kq(smb, idx_s, ci, ds + 2, t, tid); CP_COMMIT();
            } else if (ds == 8) {
                issue_v(smb, idx_s, ci, 0, tid); CP_COMMIT();
                issue_v(smb, idx_s, ci, 1, tid); CP_COMMIT();
            }
            const int st = ds % 3;
            #pragma unroll
            for (int ks = 0; ks < 4; ++ks) {
                uint32_t qf[4], kh[4], kl[4];
                uint32_t qa = smb + QH_(st) + (hg * 16 + (l & 15)) * 144 + (ks * 16 + (l >> 4) * 8) * 2;
                ldsm4(qf, qa);
                uint32_t ka = smb + KH_(st) + (kg * 16 + (l & 15)) * 144 + (ks * 16 + (l >> 4) * 8) * 2;
                ldsm4(kh, ka);
                ldsm4(kl, ka + 18432);
                mma16f(sacc[0], qf, kh[0], kh[2]); mma16f(sacc[0], qf, kl[0], kl[2]);
                mma16f(sacc[1], qf, kh[1], kh[3]); mma16f(sacc[1], qf, kl[1], kl[3]);
            }
        }

        // ===== chunked online softmax =====
        float rm0 = NEGINF, rm1 = NEGINF;
        #pragma unroll
        for (int nt = 0; nt < 2; ++nt) {
            int kb = ci * 128 + kg * 16 + nt * 8 + (l & 3) * 2;
            bool v0 = idx_s[kb] >= 0, v1 = idx_s[kb + 1] >= 0;
            float a0 = v0 ? sacc[nt][0] * SCALE_F : NEGINF;
            float a1 = v1 ? sacc[nt][1] * SCALE_F : NEGINF;
            float a2 = v0 ? sacc[nt][2] * SCALE_F : NEGINF;
            float a3 = v1 ? sacc[nt][3] * SCALE_F : NEGINF;
            sacc[nt][0] = a0; sacc[nt][1] = a1; sacc[nt][2] = a2; sacc[nt][3] = a3;
            rm0 = fmaxf(rm0, fmaxf(a0, a1));
            rm1 = fmaxf(rm1, fmaxf(a2, a3));
        }
        rm0 = fmaxf(rm0, __shfl_xor_sync(0xffffffffu, rm0, 1));
        rm0 = fmaxf(rm0, __shfl_xor_sync(0xffffffffu, rm0, 2));
        rm1 = fmaxf(rm1, __shfl_xor_sync(0xffffffffu, rm1, 1));
        rm1 = fmaxf(rm1, __shfl_xor_sync(0xffffffffu, rm1, 2));
        if ((l & 3) == 0) {
            wmax_s[kg * 64 + hg * 16 + (l >> 2)]     = rm0;
            wmax_s[kg * 64 + hg * 16 + 8 + (l >> 2)] = rm1;
        }
        __syncthreads();
        if (tid < HEADS) {
            float mo = m_s[tid];
            float mn = mo;
            #pragma unroll
            for (int g = 0; g < 8; ++g) mn = fmaxf(mn, wmax_s[g * 64 + tid]);
            float cr = __expf(mo - mn);
            m_s[tid] = mn; c_s[tid] = cr; l_s[tid] *= cr;
        }
        __syncthreads();
        float mr0 = m_s[hg * 16 + (l >> 2)];
        float mr1 = m_s[hg * 16 + 8 + (l >> 2)];
        float sum0 = 0.f, sum1 = 0.f;
        #pragma unroll
        for (int nt = 0; nt < 2; ++nt) {
            float e0 = __expf(sacc[nt][0] - mr0);
            float e1 = __expf(sacc[nt][1] - mr0);
            float e2 = __expf(sacc[nt][2] - mr1);
            float e3 = __expf(sacc[nt][3] - mr1);
            sum0 += e0 + e1; sum1 += e2 + e3;
            uint32_t col = (uint32_t)(kg * 16 + nt * 8 + (l & 3) * 2) * 2;
            uint32_t r0o = (uint32_t)(hg * 16 + (l >> 2)) * 272 + col;
            *reinterpret_cast<uint32_t*>(sm + OFF_P + r0o)           = packh2(e0, e1);
            *reinterpret_cast<uint32_t*>(sm + OFF_P + r0o + 8 * 272) = packh2(e2, e3);
        }
        sum0 += __shfl_xor_sync(0xffffffffu, sum0, 1);
        sum0 += __shfl_xor_sync(0xffffffffu, sum0, 2);
        sum1 += __shfl_xor_sync(0xffffffffu, sum1, 1);
        sum1 += __shfl_xor_sync(0xffffffffu, sum1, 2);
        if ((l & 3) == 0) {
            wsum_s[kg * 64 + hg * 16 + (l >> 2)]     = sum0;
            wsum_s[kg * 64 + hg * 16 + 8 + (l >> 2)] = sum1;
        }
        __syncthreads();
        if (tid < HEADS) {
            float acc = 0.f;
            #pragma unroll
            for (int g = 0; g < 8; ++g) acc += wsum_s[g * 64 + tid];
            l_s[tid] += acc;
        }
        float c0 = c_s[hg * 16 + (l >> 2)];
        float c1 = c_s[hg * 16 + 8 + (l >> 2)];
        #pragma unroll
        for (int nt = 0; nt < 8; ++nt) {
            o[nt][0] *= c0; o[nt][1] *= c0; o[nt][2] *= c1; o[nt][3] *= c1;
        }

        // ===== PV: 8 V tiles of 16 keys, double-buffered =====
        for (int kst = 0; kst < 8; ++kst) {
            if (kst < 7 || ci < 3) CP_WAIT(1); else CP_WAIT(0);
            __syncthreads();   // V data visible (cross-warp) + P visible (kst==0)
            uint32_t ph[4];
            uint32_t pa = smb + OFF_P + (hg * 16 + (l & 15)) * 272 +
                          (kst * 16 + (l >> 4) * 8) * 2;
            ldsm4(ph, pa);
            #pragma unroll
            for (int dvt = 0; dvt < 4; ++dvt) {
                uint32_t vh[4], vl[4];
                uint32_t va = smb + VH_(kst & 1) + (l & 15) * 1040 +
                              (kg * 64 + dvt * 16 + (l >> 4) * 8) * 2;
                ldsm4t(vh, va);
                ldsm4t(vl, va + 16640);
                float* o0 = o[dvt * 2];
                float* o1 = o[dvt * 2 + 1];
                mma16f(o0, ph, vh[0], vh[1]); mma16f(o0, ph, vl[0], vl[1]);
                mma16f(o1, ph, vh[2], vh[3]); mma16f(o1, ph, vl[2], vl[3]);
            }
            __syncthreads();   // buffer kst&1 free (all warps done)
            if (kst < 6) {
                issue_v(smb, idx_s, ci, kst + 2, tid); CP_COMMIT();
            } else if (kst == 6 && ci < 3) {
                issue_kq(smb, idx_s, ci + 1, 0, t, tid); CP_COMMIT();  // into stage0 (== V buf0)
            } else if (kst == 7 && ci < 3) {
                issue_kq(smb, idx_s, ci + 1, 1, t, tid); CP_COMMIT();  // into stage1 (== V buf1)
            }
        }
    }

    // ============ epilogue: normalize + store ============
    float n0 = 1.f / l_s[hg * 16 + (l >> 2)];
    float n1 = 1.f / l_s[hg * 16 + 8 + (l >> 2)];
    float* ob0 = out + ((size_t)t * HEADS + hg * 16 + (l >> 2)) * 512;
    float* ob1 = ob0 + 8 * 512;
    #pragma unroll
    for (int nt = 0; nt < 8; ++nt) {
        int dv = kg * 64 + nt * 8 + (l & 3) * 2;
        *reinterpret_cast<float2*>(ob0 + dv) = make_float2(o[nt][0] * n0, o[nt][1] * n0);
        *reinterpret_cast<float2*>(ob1 + dv) = make_float2(o[nt][2] * n1, o[nt][3] * n1);
    }
}

extern "C" void kernel_launch(void* const* d_in, const int* in_sizes, int n_in,
                              void* d_out, int out_size)
{
    const float* q    = (const float*)d_in[0];
    const float* kv   = (const float*)d_in[1];
    const int*   topk = (const int*)d_in[2];
    const float* sink = (const float*)d_in[3];
    float* out = (float*)d_out;

    conv_kernel<<<(2 * N2) / 256, 256>>>(kv, q);

    cudaFuncSetAttribute(mla_mma_kernel, cudaFuncAttributeMaxDynamicSharedMemorySize, SMEM_TOTAL);
    mla_mma_kernel<<<512, NTHR, SMEM_TOTAL>>>(topk, sink, out);
}

// round 14
// speedup vs baseline: 2.4652x; 1.5660x over previous
#include <cuda_runtime.h>
#include <cuda_fp16.h>
#include <cstdint>

#define NTHR   1024
#define HEADS  64
#define TOPKN  512
#define SCALE_F 0.041666666666666664f
#define NEGINF __int_as_float(0xff800000)

#define N2 4718592   // uint2 count: 32768*576*2B/8 == 512*64*576*2B/8

__device__ __align__(16) uint2 g_kh[N2];   // kv fp16
__device__ __align__(16) uint2 g_q[N2];    // q fp16

// ---- smem byte offsets ----
#define OFF_IDX   0                       // 512*4
#define OFF_M     2048
#define OFF_L     2304
#define OFF_C     2560
#define OFF_WMAX  2816                    // 8*64*4 -> 4864
#define OFF_WSUM  4864                    // 8*64*4 -> 6912
#define OFF_P     6912                    // P fp16: 64 rows * 272B -> 24320
#define KH_(s)    (24320 + (s)*18432)     // K slice 128x144B fp16; 3 stages -> 79616
#define QH_(s)    (79616 + (s)*9216)      // Q slice 64x144B fp16; 3 stages -> 107264
#define VH_(i)    (24320 + (i)*18432)     // V tile 16x1040B fp16; on K stage i
#define SMEM_TOTAL 107264

__device__ __forceinline__ uint32_t smem_u32(const void* p) {
    uint32_t a;
    asm("{ .reg .u64 t; cvta.to.shared.u64 t, %1; cvt.u32.u64 %0, t; }" : "=r"(a) : "l"(p));
    return a;
}
__device__ __forceinline__ void ldsm4(uint32_t* r, uint32_t a) {
    asm volatile("ldmatrix.sync.aligned.m8n8.x4.shared.b16 {%0,%1,%2,%3}, [%4];"
                 : "=r"(r[0]), "=r"(r[1]), "=r"(r[2]), "=r"(r[3]) : "r"(a));
}
__device__ __forceinline__ void ldsm4t(uint32_t* r, uint32_t a) {
    asm volatile("ldmatrix.sync.aligned.m8n8.x4.trans.shared.b16 {%0,%1,%2,%3}, [%4];"
                 : "=r"(r[0]), "=r"(r[1]), "=r"(r[2]), "=r"(r[3]) : "r"(a));
}
__device__ __forceinline__ void mma16f(float* d, const uint32_t* a, uint32_t b0, uint32_t b1) {
    asm volatile(
        "mma.sync.aligned.m16n8k16.row.col.f32.f16.f16.f32 "
        "{%0,%1,%2,%3}, {%4,%5,%6,%7}, {%8,%9}, {%0,%1,%2,%3};"
        : "+f"(d[0]), "+f"(d[1]), "+f"(d[2]), "+f"(d[3])
        : "r"(a[0]), "r"(a[1]), "r"(a[2]), "r"(a[3]), "r"(b0), "r"(b1));
}
__device__ __forceinline__ void cpa(uint32_t dst, const void* src, uint32_t sz) {
    asm volatile("cp.async.cg.shared.global [%0], [%1], 16, %2;"
                 :: "r"(dst), "l"(src), "r"(sz) : "memory");
}
#define CP_COMMIT() asm volatile("cp.async.commit_group;" ::: "memory")
#define CP_WAIT(n)  asm volatile("cp.async.wait_group %0;" :: "n"(n) : "memory")

__device__ __forceinline__ uint32_t packh2(float x, float y) {
    uint32_t r;
    asm("cvt.rn.f16x2.f32 %0, %1, %2;" : "=r"(r) : "f"(y), "f"(x));  // x -> low half
    return r;
}

// ================= preprocessing: fp32 -> fp16 =================
__global__ __launch_bounds__(256)
void conv_kernel(const float* __restrict__ kv, const float* __restrict__ qq)
{
    uint32_t i = blockIdx.x * 256u + threadIdx.x;
    if (i < N2) {
        float4 v = *reinterpret_cast<const float4*>(kv + (size_t)i * 4);
        g_kh[i] = make_uint2(packh2(v.x, v.y), packh2(v.z, v.w));
    } else {
        uint32_t o = i - N2;
        float4 v = *reinterpret_cast<const float4*>(qq + (size_t)o * 4);
        g_q[o] = make_uint2(packh2(v.x, v.y), packh2(v.z, v.w));
    }
}

// ================= gather issue helpers (1024 threads) =================
__device__ __forceinline__ void issue_kq(uint32_t smb, const int* idx_s,
                                         int ci, int ds, int t, int tid)
{
    const int st = ds % 3;
    {   // K slice [128 keys x 64 d] fp16: 8 threads/row, 16B each
        int row = tid >> 3, sub = tid & 7;
        int gi = idx_s[ci * 128 + row];
        uint32_t sz = gi >= 0 ? 16u : 0u;
        if (gi < 0) gi = 0;
        size_t rb = (size_t)gi * 1152 + (size_t)ds * 128 + sub * 16;
        cpa(smb + KH_(st) + row * 144 + sub * 16, (const char*)g_kh + rb, sz);
    }
    if (tid < 512) {   // Q slice [64 heads x 64 d] fp16, 3-stage
        int row = tid >> 3, sub = tid & 7;
        size_t rb = ((size_t)t * 64 + row) * 1152 + (size_t)ds * 128 + sub * 16;
        cpa(smb + QH_(st) + row * 144 + sub * 16, (const char*)g_q + rb, 16);
    }
}
__device__ __forceinline__ void issue_v(uint32_t smb, const int* idx_s,
                                        int ci, int kst, int tid)
{
    // V tile [16 keys x 512 dv] fp16: 64 threads/row, 16B each
    int row = tid >> 6, sub = tid & 63;
    int gi = idx_s[ci * 128 + kst * 16 + row];
    uint32_t sz = gi >= 0 ? 16u : 0u;
    if (gi < 0) gi = 0;
    size_t rb = (size_t)gi * 1152 + sub * 16;
    cpa(smb + VH_(kst & 1) + row * 1040 + sub * 16, (const char*)g_kh + rb, sz);
}

// ================= main attention kernel =================
__global__ __launch_bounds__(NTHR, 1)
void mla_mma_kernel(const int* __restrict__ topk,
                    const float* __restrict__ sink,
                    float* __restrict__ out)
{
    extern __shared__ char sm[];
    const uint32_t smb = smem_u32(sm);
    const int tid = threadIdx.x;
    const int w = tid >> 5, l = tid & 31;
    const int hg = w >> 3;          // 4 head groups of 16
    const int kg = w & 7;           // QK: 16-key group; PV: 64-dv group
    const int t = blockIdx.x;

    int*   idx_s  = reinterpret_cast<int*>(sm + OFF_IDX);
    float* m_s    = reinterpret_cast<float*>(sm + OFF_M);
    float* l_s    = reinterpret_cast<float*>(sm + OFF_L);
    float* c_s    = reinterpret_cast<float*>(sm + OFF_C);
    float* wmax_s = reinterpret_cast<float*>(sm + OFF_WMAX);
    float* wsum_s = reinterpret_cast<float*>(sm + OFF_WSUM);

    if (tid < 512) idx_s[tid] = __ldg(topk + (size_t)t * TOPKN + tid);
    if (tid < HEADS) { m_s[tid] = __ldg(sink + tid); l_s[tid] = 1.f; }
    __syncthreads();

    float o[8][4];
    #pragma unroll
    for (int i = 0; i < 8; ++i)
        #pragma unroll
        for (int j = 0; j < 4; ++j) o[i][j] = 0.f;

    issue_kq(smb, idx_s, 0, 0, t, tid); CP_COMMIT();
    issue_kq(smb, idx_s, 0, 1, t, tid); CP_COMMIT();

    for (int ci = 0; ci < 4; ++ci) {
        float sacc[2][4];
        #pragma unroll
        for (int i = 0; i < 2; ++i)
            #pragma unroll
            for (int j = 0; j < 4; ++j) sacc[i][j] = 0.f;

        // ===== QK: 9 d-slices of 64, 3-stage pipeline =====
        for (int ds = 0; ds < 9; ++ds) {
            if (ds < 8) CP_WAIT(1); else CP_WAIT(0);
            __syncthreads();   // data(ds) visible + all warps done with stage (ds-1)%3
            if (ds < 7) {
                issue_kq(smb, idx_s, ci, ds + 2, t, tid); CP_COMMIT();
            } else if (ds == 8) {
                issue_v(smb, idx_s, ci, 0, tid); CP_COMMIT();
                issue_v(smb, idx_s, ci, 1, tid); CP_COMMIT();
            }
            const int st = ds % 3;
            #pragma unroll
            for (int ks = 0; ks < 4; ++ks) {
                uint32_t qf[4], kh[4];
                uint32_t qa = smb + QH_(st) + (hg * 16 + (l & 15)) * 144 + (ks * 16 + (l >> 4) * 8) * 2;
                ldsm4(qf, qa);
                uint32_t ka = smb + KH_(st) + (kg * 16 + (l & 15)) * 144 + (ks * 16 + (l >> 4) * 8) * 2;
                ldsm4(kh, ka);
                mma16f(sacc[0], qf, kh[0], kh[2]);
                mma16f(sacc[1], qf, kh[1], kh[3]);
            }
        }

        // ===== chunked online softmax =====
        float rm0 = NEGINF, rm1 = NEGINF;
        #pragma unroll
        for (int nt = 0; nt < 2; ++nt) {
            int kb = ci * 128 + kg * 16 + nt * 8 + (l & 3) * 2;
            bool v0 = idx_s[kb] >= 0, v1 = idx_s[kb + 1] >= 0;
            float a0 = v0 ? sacc[nt][0] * SCALE_F : NEGINF;
            float a1 = v1 ? sacc[nt][1] * SCALE_F : NEGINF;
            float a2 = v0 ? sacc[nt][2] * SCALE_F : NEGINF;
            float a3 = v1 ? sacc[nt][3] * SCALE_F : NEGINF;
            sacc[nt][0] = a0; sacc[nt][1] = a1; sacc[nt][2] = a2; sacc[nt][3] = a3;
            rm0 = fmaxf(rm0, fmaxf(a0, a1));
            rm1 = fmaxf(rm1, fmaxf(a2, a3));
        }
        rm0 = fmaxf(rm0, __shfl_xor_sync(0xffffffffu, rm0, 1));
        rm0 = fmaxf(rm0, __shfl_xor_sync(0xffffffffu, rm0, 2));
        rm1 = fmaxf(rm1, __shfl_xor_sync(0xffffffffu, rm1, 1));
        rm1 = fmaxf(rm1, __shfl_xor_sync(0xffffffffu, rm1, 2));
        if ((l & 3) == 0) {
            wmax_s[kg * 64 + hg * 16 + (l >> 2)]     = rm0;
            wmax_s[kg * 64 + hg * 16 + 8 + (l >> 2)] = rm1;
        }
        __syncthreads();
        if (tid < HEADS) {
            float mo = m_s[tid];
            float mn = mo;
            #pragma unroll
            for (int g = 0; g < 8; ++g) mn = fmaxf(mn, wmax_s[g * 64 + tid]);
            float cr = __expf(mo - mn);
            m_s[tid] = mn; c_s[tid] = cr; l_s[tid] *= cr;
        }
        __syncthreads();
        float mr0 = m_s[hg * 16 + (l >> 2)];
        float mr1 = m_s[hg * 16 + 8 + (l >> 2)];
        float sum0 = 0.f, sum1 = 0.f;
        #pragma unroll
        for (int nt = 0; nt < 2; ++nt) {
            float e0 = __expf(sacc[nt][0] - mr0);
            float e1 = __expf(sacc[nt][1] - mr0);
            float e2 = __expf(sacc[nt][2] - mr1);
            float e3 = __expf(sacc[nt][3] - mr1);
            sum0 += e0 + e1; sum1 += e2 + e3;
            uint32_t col = (uint32_t)(kg * 16 + nt * 8 + (l & 3) * 2) * 2;
            uint32_t r0o = (uint32_t)(hg * 16 + (l >> 2)) * 272 + col;
            *reinterpret_cast<uint32_t*>(sm + OFF_P + r0o)           = packh2(e0, e1);
            *reinterpret_cast<uint32_t*>(sm + OFF_P + r0o + 8 * 272) = packh2(e2, e3);
        }
        sum0 += __shfl_xor_sync(0xffffffffu, sum0, 1);
        sum0 += __shfl_xor_sync(0xffffffffu, sum0, 2);
        sum1 += __shfl_xor_sync(0xffffffffu, sum1, 1);
        sum1 += __shfl_xor_sync(0xffffffffu, sum1, 2);
        if ((l & 3) == 0) {
            wsum_s[kg * 64 + hg * 16 + (l >> 2)]     = sum0;
            wsum_s[kg * 64 + hg * 16 + 8 + (l >> 2)] = sum1;
        }
        __syncthreads();
        if (tid < HEADS) {
            float acc = 0.f;
            #pragma unroll
            for (int g = 0; g < 8; ++g) acc += wsum_s[g * 64 + tid];
            l_s[tid] += acc;
        }
        float c0 = c_s[hg * 16 + (l >> 2)];
        float c1 = c_s[hg * 16 + 8 + (l >> 2)];
        #pragma unroll
        for (int nt = 0; nt < 8; ++nt) {
            o[nt][0] *= c0; o[nt][1] *= c0; o[nt][2] *= c1; o[nt][3] *= c1;
        }

        // ===== PV: 8 V tiles of 16 keys, double-buffered =====
        for (int kst = 0; kst < 8; ++kst) {
            if (kst < 7 || ci < 3) CP_WAIT(1); else CP_WAIT(0);
            __syncthreads();   // V data visible (cross-warp) + P visible (kst==0)
            uint32_t ph[4];
            uint32_t pa = smb + OFF_P + (hg * 16 + (l & 15)) * 272 +
                          (kst * 16 + (l >> 4) * 8) * 2;
            ldsm4(ph, pa);
            #pragma unroll
            for (int dvt = 0; dvt < 4; ++dvt) {
                uint32_t vh[4];
                uint32_t va = smb + VH_(kst & 1) + (l & 15) * 1040 +
                              (kg * 64 + dvt * 16 + (l >> 4) * 8) * 2;
                ldsm4t(vh, va);
                mma16f(o[dvt * 2],     ph, vh[0], vh[1]);
                mma16f(o[dvt * 2 + 1], ph, vh[2], vh[3]);
            }
            __syncthreads();   // buffer kst&1 free (all warps done)
            if (kst < 6) {
                issue_v(smb, idx_s, ci, kst + 2, tid); CP_COMMIT();
            } else if (kst == 6 && ci < 3) {
                issue_kq(smb, idx_s, ci + 1, 0, t, tid); CP_COMMIT();  // into stage0 (== V buf0)
            } else if (kst == 7 && ci < 3) {
                issue_kq(smb, idx_s, ci + 1, 1, t, tid); CP_COMMIT();  // into stage1 (== V buf1)
            }
        }
    }

    // ============ epilogue: normalize + store ============
    float n0 = 1.f / l_s[hg * 16 + (l >> 2)];
    float n1 = 1.f / l_s[hg * 16 + 8 + (l >> 2)];
    float* ob0 = out + ((size_t)t * HEADS + hg * 16 + (l >> 2)) * 512;
    float* ob1 = ob0 + 8 * 512;
    #pragma unroll
    for (int nt = 0; nt < 8; ++nt) {
        int dv = kg * 64 + nt * 8 + (l & 3) * 2;
        *reinterpret_cast<float2*>(ob0 + dv) = make_float2(o[nt][0] * n0, o[nt][1] * n0);
        *reinterpret_cast<float2*>(ob1 + dv) = make_float2(o[nt][2] * n1, o[nt][3] * n1);
    }
}

extern "C" void kernel_launch(void* const* d_in, const int* in_sizes, int n_in,
                              void* d_out, int out_size)
{
    const float* q    = (const float*)d_in[0];
    const float* kv   = (const float*)d_in[1];
    const int*   topk = (const int*)d_in[2];
    const float* sink = (const float*)d_in[3];
    float* out = (float*)d_out;

    conv_kernel<<<(2 * N2) / 256, 256>>>(kv, q);

    cudaFuncSetAttribute(mla_mma_kernel, cudaFuncAttributeMaxDynamicSharedMemorySize, SMEM_TOTAL);
    mla_mma_kernel<<<512, NTHR, SMEM_TOTAL>>>(topk, sink, out);
}